// round 15
// baseline (speedup 1.0000x reference)
#include <cuda_runtime.h>

#define N_SAMPLES 65536
#define TPB 256
#define EPT 32
#define TILE (TPB * EPT)            // 8192 samples per block
#define CHUNKS (N_SAMPLES / TILE)   // 8 blocks per row

#define TWOPI_F 6.28318530717958647692f   /* fl32(2*pi) */
#define INV2PI_F 0.15915494309189533576f
#define INV2PI_D 0.15915494309189533576888376337251

// fp32 range constants, bit-exact vs reference's (float)np.log2 chain:
//   fl32(log2(32.7))              = 10551230 * 2^-21
//   fl32(log2(523.25)-log2(32.7)) =  8388897 * 2^-21
#define LO_F0 5.0312185287475586f
#define D_F0  4.0001378059387207f

__device__ __forceinline__ float2 ds_from_d(double x) {
    float h = (float)x;
    return make_float2(h, (float)(x - (double)h));
}

// exp2(x), |x| <= ~10, rel err ~1e-14 (deg-11 Taylor + exact 2^k)
__device__ __forceinline__ double exp2d(double x) {
    double k = rint(x);
    double f = x - k;                         // |f| <= 0.5, exact
    double p = 4.4455382718708125e-10;
    p = fma(p, f, 7.0549116208011210e-09);
    p = fma(p, f, 1.0178086009239699e-07);
    p = fma(p, f, 1.3215486790144307e-06);
    p = fma(p, f, 1.5252733804059837e-05);
    p = fma(p, f, 1.5403530393381629e-04);
    p = fma(p, f, 1.3333558146428443e-03);
    p = fma(p, f, 9.6181291076284772e-03);
    p = fma(p, f, 5.5504108664821580e-02);
    p = fma(p, f, 2.4022650695910071e-01);
    p = fma(p, f, 6.9314718055994531e-01);
    p = fma(p, f, 1.0);
    long long ki = (long long)k;
    return __longlong_as_double(__double_as_longlong(p) + (ki << 52));
}

// 1/x via fp32 rcp + two DP Newton steps
__device__ __forceinline__ double drcp(double x) {
    double y = (double)__frcp_rn((float)x);
    y = y * fma(-x, y, 2.0);
    y = y * fma(-x, y, 2.0);
    return y;
}

// cos(x), |x| <= ~8, abs err ~4e-9
__device__ __forceinline__ double dcos_red(double x) {
    const double TWOPI_D = 6.283185307179586476925286766559;
    double q = rint(x * INV2PI_D);
    double r = fma(-q, TWOPI_D, x);
    double u = r * r;
    double p = -1.5619206968586225e-16;
    p = fma(p, u,  4.7794773323873853e-14);
    p = fma(p, u, -1.1470745597729725e-11);
    p = fma(p, u,  2.0876756987868098e-09);
    p = fma(p, u, -2.7557319223985893e-07);
    p = fma(p, u,  2.4801587301587302e-05);
    p = fma(p, u, -1.3888888888888889e-03);
    p = fma(p, u,  4.1666666666666664e-02);
    p = fma(p, u, -0.5);
    return fma(p, u, 1.0);
}

// fm frequency (rad/sample) from its uniform draw
__device__ __forceinline__ double fm_rad_per_sample(float u) {
    float xf = __fadd_rn(__fmul_rn(u, 4.0f), -1.0f);
    float fm_hz = (float)exp2d((double)xf);
    return (double)__fmul_rn(TWOPI_F, fm_hz) * (1.0 / 44100.0);
}

// frac(c*n + p) in turns via double-single fp32 arithmetic.
__device__ __forceinline__ float2 ds_anchor(float2 c, float2 p, float n) {
    float ph = __fmul_rn(c.x, n);
    float pe = fmaf(c.x, n, -ph);            // exact twoProd residual
    float pl = fmaf(c.y, n, pe);
    float s  = ph + p.x;                     // two-sum
    float bb = s - ph;
    float er = (ph - (s - bb)) + (p.x - bb);
    float lo = er + pl + p.y;
    float q  = rintf(s);
    float rh = s - q;                        // exact
    float t  = rh + lo;
    float tl = lo - (t - rh);
    return make_float2(t, tl);
}

// cos(2*pi*(x.hi+x.lo)) for |x.hi| <= 0.5+eps; abs err ~1.2e-7
__device__ __forceinline__ float cos2pi(float2 x) {
    float k = rintf(2.0f * x.x);
    float z = (x.x - 0.5f * k) + x.y;
    float u = z * z;
    float pp = fmaf(7.9033069f, u, -26.4262561f);
    pp = fmaf(pp, u,  60.2446416f);
    pp = fmaf(pp, u, -85.4568172f);
    pp = fmaf(pp, u,  64.9393940f);
    pp = fmaf(pp, u, -19.7392088f);
    float c = fmaf(pp, u, 1.0f);
    float sgn = fmaf(-2.0f, fabsf(k), 1.0f);
    return c * sgn;
}

// XOR swizzle at float4 granularity (conflict-free both phases)
__device__ __forceinline__ int sw(int v) { return v ^ ((v >> 3) & 7); }

__global__ __launch_bounds__(TPB, 6)
void amfm_kernel(const float* __restrict__ theta_am,
                 const float* __restrict__ theta_fm,
                 const float* __restrict__ phase,
                 const float* __restrict__ phase_am,
                 const float* __restrict__ phase_fm,
                 const float* __restrict__ u_am_mi,
                 const float* __restrict__ u_fm_hz,
                 const float* __restrict__ u_f0_hz,
                 float* __restrict__ out)
{
    __shared__ float4 tile4[TILE / 4];       // 32 KB staging
    __shared__ float4 srow[5];               // per-row constants

    const int bx    = blockIdx.x;
    const int row   = bx >> 3;               // / CHUNKS
    const int chunk = bx & (CHUNKS - 1);
    const int tid   = threadIdx.x;
    const double INV_SR = 1.0 / 44100.0;

    // ---- in-block per-row setup: 3 lanes, short DP chains, no libm ----
    if (tid == 0) {
        // AM chain (fp32-precision targets only)
        float xa = __fadd_rn(__fmul_rn(theta_am[row], 4.0f), -1.0f);
        float am_hz = (float)exp2d((double)xa);
        double am_rad = (double)__fmul_rn(TWOPI_F, am_hz) * INV_SR;
        srow[4] = make_float4(
            (float)(am_rad * INV2PI_D),                                    // amt_turns
            (float)((double)__fmul_rn(TWOPI_F, phase_am[row]) * INV2PI_D), // pam_turns
            (float)(16.0 * am_rad),                                        // am16
            0.5f * u_am_mi[row]);                                          // hmiam
    } else if (tid == 32) {
        // FM chain
        double dfm = fm_rad_per_sample(u_fm_hz[row]);
        double half = 0.5 * dfm;
        double pfm = (double)__fmul_rn(TWOPI_F, phase_fm[row]);
        double c2  = pfm - half;
        float2 dfm_t = ds_from_d(dfm * INV2PI_D);
        float2 pfm_t = ds_from_d(pfm * INV2PI_D);
        float2 hd_t  = ds_from_d(half * INV2PI_D);
        srow[1] = make_float4(dfm_t.x, dfm_t.y, pfm_t.x, pfm_t.y);
        srow[2] = make_float4(hd_t.x, hd_t.y, (float)dcos_red(c2),
                              (float)(16.0 * dfm));
    } else if (tid == 64) {
        // carrier chain (range constants hardcoded; also redoes fm freq for mk)
        float x0 = __fadd_rn(__fmul_rn(u_f0_hz[row], D_F0), LO_F0);
        float f0_hz = (float)exp2d((double)x0);
        double base = (double)__fmul_rn(TWOPI_F, f0_hz) * INV_SR;  // rad/sample
        double mfm  = base * (double)theta_fm[row];                // rad/sample
        double dfm  = fm_rad_per_sample(u_fm_hz[row]);
        double half = 0.5 * dfm;
        double h2   = half * half;
        double sinh = half * fma(h2, fma(h2, (1.0/120.0), -(1.0/6.0)), 1.0);
        double K2   = 0.5 * drcp(sinh);
        float2 base_t = ds_from_d(base * INV2PI_D);
        float2 p0_t = ds_from_d((double)__fmul_rn(TWOPI_F, phase[row]) * INV2PI_D);
        float2 mk   = ds_from_d(mfm * K2 * INV2PI_D);
        srow[0] = make_float4(base_t.x, base_t.y, p0_t.x, p0_t.y);
        srow[3] = make_float4(mk.x, mk.y, (float)base, (float)mfm);
    }
    __syncthreads();

    const float4 q0 = srow[0];               // base_t | p0_t
    const float4 q1 = srow[1];               // dfm_t | pfm_t
    const float4 q2 = srow[2];               // hd_t | cosc2 | fmt16
    const float4 q3 = srow[3];               // mk | basef | mfmf
    const float4 q4 = srow[4];               // am constants

    const float2 base_t = make_float2(q0.x, q0.y);
    const float2 p0_t   = make_float2(q0.z, q0.w);
    const float2 dfm_t  = make_float2(q1.x, q1.y);
    const float2 pfm_t  = make_float2(q1.z, q1.w);
    const float2 hd_t   = make_float2(q2.x, q2.y);
    const float  cosc2  = q2.z, fmt16 = q2.w;
    const float  mkh = q3.x, mkl = q3.y, basef = q3.z, mfmf = q3.w;
    const float  amt_turns = q4.x, pam_turns = q4.y, am16 = q4.z, hmiam = q4.w;

    const float n = (float)(chunk * TILE + tid * EPT);   // exact integer

    // ---- fm phase anchor (DS, turns): ftt = frac(dfm*n + pfm) ----
    float2 ftt = ds_anchor(dfm_t, pfm_t, n);

    // ---- th = ftt - hd  (DS subtract; cos argument n*dfm + c2) ----
    float sh = ftt.x - hd_t.x;
    float sb = sh - ftt.x;
    float se = (ftt.x - (sh - sb)) - (hd_t.x + sb);
    float sl = se + (ftt.y - hd_t.y);
    float cth = cos2pi(make_float2(sh, sl));

    // ---- modulation: mod = mk * (cosc2 - cth)  (DS) ----
    float dd = cosc2 - cth;                  // twoDiff
    float db = dd - cosc2;
    float de = (cosc2 - (dd - db)) - (cth + db);
    float mh = __fmul_rn(mkh, dd);
    float ml = fmaf(mkh, dd, -mh) + fmaf(mkl, dd, __fmul_rn(mkh, de));

    // ---- carrier anchor: frac(base*n + p0 + mod), to radians ----
    float gh = __fmul_rn(base_t.x, n);
    float ge = fmaf(base_t.x, n, -gh);
    float gl = fmaf(base_t.y, n, ge);
    float s1 = gh + p0_t.x;
    float b1 = s1 - gh;
    float e1 = (gh - (s1 - b1)) + (p0_t.x - b1);
    float s2 = s1 + mh;
    float b2 = s2 - s1;
    float e2 = (s1 - (s2 - b2)) + (mh - b2);
    float lo = gl + p0_t.y + e1 + ml + e2;
    float q  = rintf(s2);
    float S  = TWOPI_F * ((s2 - q) + lo);    // carrier phase anchor (rad)

    // ---- fm modulator endpoints at k=0,16,32 ----
    float ft   = TWOPI_F * (ftt.x + ftt.y);
    float sf0  = __sinf(ft);
    float sf16 = __sinf(ft + fmt16);
    float sf32 = __sinf(ft + (fmt16 + fmt16));
    float i0   = fmaf(mfmf, sf0,  basef);    // increment at k=0
    float i16  = fmaf(mfmf, sf16, basef);
    float i32  = fmaf(mfmf, sf32, basef);
    float d2   = (i16 - i0)  * 0.0625f;      // seg 0 curvature
    float d2b  = (i32 - i16) * 0.0625f;      // seg 1 curvature

    // ---- am envelope endpoints at k=0,16,32 ----
    float ap   = fmaf(amt_turns, n, pam_turns);
    float ar   = TWOPI_F * (ap - rintf(ap));
    float sa0  = __sinf(ar);
    float sa16 = __sinf(ar + am16);
    float sa32 = __sinf(ar + (am16 + am16));
    float W0   = fmaf(hmiam, sa0,  0.5f);
    float W16  = fmaf(hmiam, sa16, 0.5f);
    float W32  = fmaf(hmiam, sa32, 0.5f);
    float dw   = (W16 - W0)  * 0.0625f;
    float dwb  = (W32 - W16) * 0.0625f;

    // Closed-form per segment, m = 1..16 (immediates after unroll):
    //   s_m = S + m*A + m^2*B,  w_m = W + (m-1)*dw
    float A0 = fmaf(-0.5f, d2, i0);
    float B0 = 0.5f * d2;
    float S1 = fmaf(256.0f, B0, fmaf(16.0f, A0, S));
    S1 = fmaf(-rintf(S1 * INV2PI_F), TWOPI_F, S1);
    float A1 = fmaf(-0.5f, d2b, i16);
    float B1 = 0.5f * d2b;
    float W1 = fmaf(16.0f, dw, W0);

    // ---- synthesize 32 samples: 3 imm-FFMA + 1 FMUL + 1 MUFU per sample ----
    #pragma unroll
    for (int g = 0; g < 8; g++) {
        const float Sg = (g < 4) ? S  : S1;
        const float Ag = (g < 4) ? A0 : A1;
        const float Bg = (g < 4) ? B0 : B1;
        const float Wg = (g < 4) ? W0 : W1;
        const float Dg = (g < 4) ? dw : dwb;
        float v[4];
        #pragma unroll
        for (int j = 0; j < 4; j++) {
            const int   m   = (g & 3) * 4 + j + 1;      // 1..16 within segment
            const float mf  = (float)m;
            const float m2f = (float)(m * m);
            float sm = fmaf(m2f, Bg, fmaf(mf, Ag, Sg));
            float xc = __sinf(sm);                      // carrier
            float wv = fmaf((float)(m - 1), Dg, Wg);
            v[j] = xc * wv;
        }
        tile4[sw(8 * tid + g)] = make_float4(v[0], v[1], v[2], v[3]);
    }
    __syncthreads();

    // ---- coalesced writeback: warp writes 512B contiguous per STG.128 ----
    float4* __restrict__ o4 =
        (float4*)(out + (size_t)row * N_SAMPLES + chunk * TILE);
    #pragma unroll
    for (int r = 0; r < 8; r++) {
        o4[r * 256 + tid] = tile4[sw(r * 256 + tid)];
    }
}

extern "C" void kernel_launch(void* const* d_in, const int* in_sizes, int n_in,
                              void* d_out, int out_size) {
    const int B = in_sizes[0];   // 256 rows
    amfm_kernel<<<B * CHUNKS, TPB>>>(
        (const float*)d_in[0],   // theta_am_0to1
        (const float*)d_in[1],   // theta_fm_0to1
        (const float*)d_in[2],   // phase
        (const float*)d_in[3],   // phase_am
        (const float*)d_in[4],   // phase_fm
        (const float*)d_in[5],   // u_am_mi
        (const float*)d_in[6],   // u_fm_hz
        (const float*)d_in[7],   // u_f0_hz
        (float*)d_out);
}

// round 17
// speedup vs baseline: 1.5431x; 1.5431x over previous
#include <cuda_runtime.h>
#include <cstdint>

#define N_SAMPLES 65536
#define TPB 256
#define EPT 32
#define TILE (TPB * EPT)            // 8192 samples per block
#define CHUNKS (N_SAMPLES / TILE)   // 8 blocks per row

#define TWOPI_F 6.28318530717958647692f   /* fl32(2*pi) */
#define INV2PI_F 0.15915494309189533576f

// fp32 range constants, bit-exact vs reference's (float)np.log2 chain:
#define LO_F0 5.0312185287475586f
#define D_F0  4.0001378059387207f

// double-single value
struct dsf { float h, l; };

// compile-time split of a double literal into a DS pair (no runtime FP64)
#define DSC(d) dsf{(float)(d), (float)((d) - (double)(float)(d))}

__device__ __forceinline__ dsf ds_add(dsf a, dsf b) {
    float s  = a.h + b.h;
    float bb = s - a.h;
    float e  = (a.h - (s - bb)) + (b.h - bb);
    float lo = e + a.l + b.l;
    float hh = s + lo;
    return dsf{hh, lo - (hh - s)};
}
__device__ __forceinline__ dsf ds_mul(dsf a, dsf b) {
    float p  = __fmul_rn(a.h, b.h);
    float e  = fmaf(a.h, b.h, -p);
    float lo = fmaf(a.h, b.l, fmaf(a.l, b.h, e));
    float hh = p + lo;
    return dsf{hh, lo - (hh - p)};
}
__device__ __forceinline__ dsf ds_mulf(dsf a, float b) {
    float p  = __fmul_rn(a.h, b);
    float e  = fmaf(a.h, b, -p);
    float lo = fmaf(a.l, b, e);
    float hh = p + lo;
    return dsf{hh, lo - (hh - p)};
}
__device__ __forceinline__ float ds_col(dsf a) { return a.h + a.l; }

// 1/x in DS from fp32 rcp + one DS Newton step (rel ~2^-40)
__device__ __forceinline__ dsf ds_rcp(dsf x) {
    float y0 = __frcp_rn(x.h);
    dsf xy = ds_mulf(x, y0);
    float e = (1.0f - xy.h) - xy.l;          // Sterbenz: 1-xy.h exact
    float lo = y0 * e;
    float hh = y0 + lo;
    return dsf{hh, lo - (hh - y0)};
}

// exp2(x) in DS for fp32 x in [-1, 9.1]; rel err ~2^-40
__device__ __forceinline__ dsf exp2_ds(float x) {
    float k = rintf(x);
    float f = x - k;                          // exact, |f| <= 0.5
    dsf p = DSC(4.4455382718708063e-10);
    p = ds_add(ds_mulf(p, f), DSC(7.0549116208011233e-09));
    p = ds_add(ds_mulf(p, f), DSC(1.0178086009239699e-07));
    p = ds_add(ds_mulf(p, f), DSC(1.3215486790144309e-06));
    p = ds_add(ds_mulf(p, f), DSC(1.5252733804059840e-05));
    p = ds_add(ds_mulf(p, f), DSC(1.5403530393381609e-04));
    p = ds_add(ds_mulf(p, f), DSC(1.3333558146428443e-03));
    p = ds_add(ds_mulf(p, f), DSC(9.6181291076284771e-03));
    p = ds_add(ds_mulf(p, f), DSC(5.5504108664821576e-02));
    p = ds_add(ds_mulf(p, f), DSC(2.4022650695910071e-01));
    p = ds_add(ds_mulf(p, f), DSC(6.9314718055994531e-01));
    p = ds_add(ds_mulf(p, f), DSC(1.0));
    float sc = __uint_as_float((unsigned int)(127 + (int)k) << 23); // exact 2^k
    return dsf{p.h * sc, p.l * sc};
}

// cos(2*pi*(x.hi+x.lo)) for |x.hi| <= 0.5+eps; abs err ~1.2e-7
__device__ __forceinline__ float cos2pi(float2 x) {
    float k = rintf(2.0f * x.x);
    float z = (x.x - 0.5f * k) + x.y;
    float u = z * z;
    float pp = fmaf(7.9033069f, u, -26.4262561f);
    pp = fmaf(pp, u,  60.2446416f);
    pp = fmaf(pp, u, -85.4568172f);
    pp = fmaf(pp, u,  64.9393940f);
    pp = fmaf(pp, u, -19.7392088f);
    float c = fmaf(pp, u, 1.0f);
    float sgn = fmaf(-2.0f, fabsf(k), 1.0f);
    return c * sgn;
}

// frac(c*n + p) in turns via double-single fp32 arithmetic.
__device__ __forceinline__ float2 ds_anchor(float2 c, float2 p, float n) {
    float ph = __fmul_rn(c.x, n);
    float pe = fmaf(c.x, n, -ph);            // exact twoProd residual
    float pl = fmaf(c.y, n, pe);
    float s  = ph + p.x;                     // two-sum
    float bb = s - ph;
    float er = (ph - (s - bb)) + (p.x - bb);
    float lo = er + pl + p.y;
    float q  = rintf(s);
    float rh = s - q;                        // exact
    float t  = rh + lo;
    float tl = lo - (t - rh);
    return make_float2(t, tl);
}

// XOR swizzle at float4 granularity (conflict-free both phases)
__device__ __forceinline__ int sw(int v) { return v ^ ((v >> 3) & 7); }

__global__ __launch_bounds__(TPB, 6)
void amfm_kernel(const float* __restrict__ theta_am,
                 const float* __restrict__ theta_fm,
                 const float* __restrict__ phase,
                 const float* __restrict__ phase_am,
                 const float* __restrict__ phase_fm,
                 const float* __restrict__ u_am_mi,
                 const float* __restrict__ u_fm_hz,
                 const float* __restrict__ u_f0_hz,
                 float* __restrict__ out)
{
    __shared__ float4 tile4[TILE / 4];       // 32 KB staging
    __shared__ float4 srow[5];               // per-row constants

    const int bx    = blockIdx.x;
    const int row   = bx >> 3;               // / CHUNKS
    const int chunk = bx & (CHUNKS - 1);
    const int tid   = threadIdx.x;

    // DS constants (compile-time split; no runtime FP64 anywhere)
    const dsf K_TURN  = DSC(3.6089528412921540e-06);  // 1/(44100*2pi)
    const dsf K_RAD   = DSC(2.2675736961451247e-05);  // 1/44100
    const dsf K_I2PI  = DSC(0.15915494309189535);     // 1/(2pi)
    const dsf K_HI2PI = DSC(0.07957747154594767);     // 0.5/(2pi)

    // ---- in-block per-row setup: 3 lanes in 3 warps, pure fp32/DS ----
    if (tid == 0) {
        // AM chain (fp32-precision targets only)
        float xa = __fadd_rn(__fmul_rn(theta_am[row], 4.0f), -1.0f);
        float am_hz = ds_col(exp2_ds(xa));
        float wam = __fmul_rn(TWOPI_F, am_hz);
        dsf amt = ds_mulf(K_TURN, wam);                     // turns/sample
        float pam = __fmul_rn(TWOPI_F, phase_am[row]);
        srow[4] = make_float4(ds_col(amt),
                              ds_col(ds_mulf(K_I2PI, pam)),        // pam_turns
                              16.0f * ds_col(ds_mulf(K_RAD, wam)), // am16 rad
                              0.5f * u_am_mi[row]);                // hmiam
    } else if (tid == 32) {
        // FM chain
        float xf = __fadd_rn(__fmul_rn(u_fm_hz[row], 4.0f), -1.0f);
        float fm_hz = ds_col(exp2_ds(xf));
        float wfm = __fmul_rn(TWOPI_F, fm_hz);
        dsf dfm_t = ds_mulf(K_TURN, wfm);                   // turns/sample
        dsf hd_t  = dsf{0.5f * dfm_t.h, 0.5f * dfm_t.l};    // exact halving
        float pfm = __fmul_rn(TWOPI_F, phase_fm[row]);
        dsf pfm_t = ds_mulf(K_I2PI, pfm);
        // c2 (turns) = pfm_t - hd_t, frac-reduced for cos2pi
        dsf c2 = ds_add(pfm_t, dsf{-hd_t.h, -hd_t.l});
        float c2h = c2.h - rintf(c2.h);                      // exact
        float cosc2 = cos2pi(make_float2(c2h, c2.l));
        float fmt16 = 16.0f * ds_col(ds_mulf(K_RAD, wfm));   // 16*dfm rad
        srow[1] = make_float4(dfm_t.h, dfm_t.l, pfm_t.h, pfm_t.l);
        srow[2] = make_float4(hd_t.h, hd_t.l, cosc2, fmt16);
    } else if (tid == 64) {
        // carrier chain (redoes fm frequency to finish mk locally)
        float x0 = __fadd_rn(__fmul_rn(u_f0_hz[row], D_F0), LO_F0);
        float f0_hz = ds_col(exp2_ds(x0));
        float w0 = __fmul_rn(TWOPI_F, f0_hz);
        dsf base_t  = ds_mulf(K_TURN, w0);                  // turns/sample
        dsf base_rd = ds_mulf(K_RAD,  w0);                  // rad/sample
        dsf mfm_rd  = ds_mulf(base_rd, theta_fm[row]);      // rad/sample
        float p0 = __fmul_rn(TWOPI_F, phase[row]);
        dsf p0_t = ds_mulf(K_I2PI, p0);
        // K2/(2pi) = (0.5/2pi) / sin(half), half = dfm_rad/2 (tiny)
        float xf = __fadd_rn(__fmul_rn(u_fm_hz[row], 4.0f), -1.0f);
        float wfm = __fmul_rn(TWOPI_F, ds_col(exp2_ds(xf)));
        dsf half = ds_mulf(K_RAD, 0.5f * wfm);              // <= 5.7e-4 rad
        float h2 = half.h * half.h;
        float corr = -h2 * (1.0f/6.0f) * fmaf(-h2, 0.05f, 1.0f); // ~ -h^2/6
        dsf sinh = ds_add(half, ds_mulf(half, corr));       // sin(half), DS
        dsf k2t  = ds_mul(K_HI2PI, ds_rcp(sinh));           // K2/(2pi)
        dsf mk   = ds_mul(mfm_rd, k2t);                     // turns gain
        srow[0] = make_float4(base_t.h, base_t.l, p0_t.h, p0_t.l);
        srow[3] = make_float4(mk.h, mk.l, ds_col(base_rd), ds_col(mfm_rd));
    }
    __syncthreads();

    const float4 q0 = srow[0];               // base_t | p0_t
    const float4 q1 = srow[1];               // dfm_t | pfm_t
    const float4 q2 = srow[2];               // hd_t | cosc2 | fmt16
    const float4 q3 = srow[3];               // mk | basef | mfmf
    const float4 q4 = srow[4];               // am constants

    const float2 base_t = make_float2(q0.x, q0.y);
    const float2 p0_t   = make_float2(q0.z, q0.w);
    const float2 dfm_t  = make_float2(q1.x, q1.y);
    const float2 pfm_t  = make_float2(q1.z, q1.w);
    const float2 hd_t   = make_float2(q2.x, q2.y);
    const float  cosc2  = q2.z, fmt16 = q2.w;
    const float  mkh = q3.x, mkl = q3.y, basef = q3.z, mfmf = q3.w;
    const float  amt_turns = q4.x, pam_turns = q4.y, am16 = q4.z, hmiam = q4.w;

    const float n = (float)(chunk * TILE + tid * EPT);   // exact integer

    // ---- fm phase anchor (DS, turns): ftt = frac(dfm*n + pfm) ----
    float2 ftt = ds_anchor(dfm_t, pfm_t, n);

    // ---- th = ftt - hd  (DS subtract; cos argument n*dfm + c2) ----
    float sh = ftt.x - hd_t.x;
    float sb = sh - ftt.x;
    float se = (ftt.x - (sh - sb)) - (hd_t.x + sb);
    float sl = se + (ftt.y - hd_t.y);
    float cth = cos2pi(make_float2(sh, sl));

    // ---- modulation: mod = mk * (cosc2 - cth)  (DS) ----
    float dd = cosc2 - cth;                  // twoDiff
    float db = dd - cosc2;
    float de = (cosc2 - (dd - db)) - (cth + db);
    float mh = __fmul_rn(mkh, dd);
    float ml = fmaf(mkh, dd, -mh) + fmaf(mkl, dd, __fmul_rn(mkh, de));

    // ---- carrier anchor: frac(base*n + p0 + mod), to radians ----
    float gh = __fmul_rn(base_t.x, n);
    float ge = fmaf(base_t.x, n, -gh);
    float gl = fmaf(base_t.y, n, ge);
    float s1 = gh + p0_t.x;
    float b1 = s1 - gh;
    float e1 = (gh - (s1 - b1)) + (p0_t.x - b1);
    float s2 = s1 + mh;
    float b2 = s2 - s1;
    float e2 = (s1 - (s2 - b2)) + (mh - b2);
    float lo = gl + p0_t.y + e1 + ml + e2;
    float q  = rintf(s2);
    float S  = TWOPI_F * ((s2 - q) + lo);    // carrier phase anchor (rad)

    // ---- fm modulator endpoints at k=0,16,32 ----
    float ft   = TWOPI_F * (ftt.x + ftt.y);
    float sf0  = __sinf(ft);
    float sf16 = __sinf(ft + fmt16);
    float sf32 = __sinf(ft + (fmt16 + fmt16));
    float i0   = fmaf(mfmf, sf0,  basef);    // increment at k=0
    float i16  = fmaf(mfmf, sf16, basef);
    float i32  = fmaf(mfmf, sf32, basef);
    float d2   = (i16 - i0)  * 0.0625f;      // seg 0 curvature
    float d2b  = (i32 - i16) * 0.0625f;      // seg 1 curvature

    // ---- am envelope endpoints at k=0,16,32 ----
    float ap   = fmaf(amt_turns, n, pam_turns);
    float ar   = TWOPI_F * (ap - rintf(ap));
    float sa0  = __sinf(ar);
    float sa16 = __sinf(ar + am16);
    float sa32 = __sinf(ar + (am16 + am16));
    float W0   = fmaf(hmiam, sa0,  0.5f);
    float W16  = fmaf(hmiam, sa16, 0.5f);
    float W32  = fmaf(hmiam, sa32, 0.5f);
    float dw   = (W16 - W0)  * 0.0625f;
    float dwb  = (W32 - W16) * 0.0625f;

    // Closed-form per segment, m = 1..16 (immediates after unroll):
    //   s_m = S + m*A + m^2*B,  w_m = W + (m-1)*dw
    float A0 = fmaf(-0.5f, d2, i0);
    float B0 = 0.5f * d2;
    float S1 = fmaf(256.0f, B0, fmaf(16.0f, A0, S));
    S1 = fmaf(-rintf(S1 * INV2PI_F), TWOPI_F, S1);
    float A1 = fmaf(-0.5f, d2b, i16);
    float B1 = 0.5f * d2b;
    float W1 = fmaf(16.0f, dw, W0);

    // ---- synthesize 32 samples: 3 imm-FFMA + 1 FMUL + 1 MUFU per sample ----
    #pragma unroll
    for (int g = 0; g < 8; g++) {
        const float Sg = (g < 4) ? S  : S1;
        const float Ag = (g < 4) ? A0 : A1;
        const float Bg = (g < 4) ? B0 : B1;
        const float Wg = (g < 4) ? W0 : W1;
        const float Dg = (g < 4) ? dw : dwb;
        float v[4];
        #pragma unroll
        for (int j = 0; j < 4; j++) {
            const int   m   = (g & 3) * 4 + j + 1;      // 1..16 within segment
            const float mf  = (float)m;
            const float m2f = (float)(m * m);
            float sm = fmaf(m2f, Bg, fmaf(mf, Ag, Sg));
            float xc = __sinf(sm);                      // carrier
            float wv = fmaf((float)(m - 1), Dg, Wg);
            v[j] = xc * wv;
        }
        tile4[sw(8 * tid + g)] = make_float4(v[0], v[1], v[2], v[3]);
    }
    __syncthreads();

    // ---- coalesced writeback: warp writes 512B contiguous per STG.128 ----
    float4* __restrict__ o4 =
        (float4*)(out + (size_t)row * N_SAMPLES + chunk * TILE);
    #pragma unroll
    for (int r = 0; r < 8; r++) {
        o4[r * 256 + tid] = tile4[sw(r * 256 + tid)];
    }
}

extern "C" void kernel_launch(void* const* d_in, const int* in_sizes, int n_in,
                              void* d_out, int out_size) {
    const int B = in_sizes[0];   // 256 rows
    amfm_kernel<<<B * CHUNKS, TPB>>>(
        (const float*)d_in[0],   // theta_am_0to1
        (const float*)d_in[1],   // theta_fm_0to1
        (const float*)d_in[2],   // phase
        (const float*)d_in[3],   // phase_am
        (const float*)d_in[4],   // phase_fm
        (const float*)d_in[5],   // u_am_mi
        (const float*)d_in[6],   // u_fm_hz
        (const float*)d_in[7],   // u_f0_hz
        (float*)d_out);
}